// round 1
// baseline (speedup 1.0000x reference)
#include <cuda_runtime.h>

// Problem constants (fixed by the reference)
#define NN 100000      // nodes
#define DD 64          // feature dim
#define EE 800000      // edges
#define LLAYERS 2

// ---------------------------------------------------------------------------
// Scratch (device globals; no allocation anywhere)
// ---------------------------------------------------------------------------
__device__ float d_e[3][2][NN * DD];   // [branch][ping-pong][N*D]
__device__ float d_P[NN * DD];         // e1 @ W1_top + b1
__device__ float d_Q[NN * DD];         // e1 @ W1_bot
__device__ float d_gated[NN * DD];     // gate * e2
__device__ float d_w[EE];              // edge weights w, later vals1 in place
__device__ float d_row[NN];            // segment sum of w by h

// ---------------------------------------------------------------------------
// Helpers
// ---------------------------------------------------------------------------
__device__ __forceinline__ void red_add_v4(float* addr, float x, float y,
                                           float z, float w) {
    asm volatile("red.global.add.v4.f32 [%0], {%1,%2,%3,%4};"
                 :: "l"(addr), "f"(x), "f"(y), "f"(z), "f"(w) : "memory");
}

__device__ __forceinline__ float sigmoidf(float x) {
    return 1.0f / (1.0f + expf(-x));
}

// ---------------------------------------------------------------------------
// K_init: e0=e1=e2=emb0, s0=s1=s2=emb0 (d_out)
// ---------------------------------------------------------------------------
__global__ void k_init(const float4* __restrict__ emb0, float4* __restrict__ out) {
    int i = blockIdx.x * blockDim.x + threadIdx.x;
    if (i >= NN * DD / 4) return;
    float4 v = emb0[i];
    ((float4*)d_e[0][0])[i] = v;
    ((float4*)d_e[1][0])[i] = v;
    ((float4*)d_e[2][0])[i] = v;
    out[i] = v;
    out[i + NN * (DD / 4)] = v;
    out[i + 2 * NN * (DD / 4)] = v;
}

// ---------------------------------------------------------------------------
// K_node_pq: P = e1 @ W1_top + b1 ; Q = e1 @ W1_bot
// Also: zero d_row, copy cur->nxt for all 3 branches (accumulator init).
// warp-per-node; lane handles output cols (2*lane, 2*lane+1).
// ---------------------------------------------------------------------------
__global__ __launch_bounds__(256) void k_node_pq(
    const float* __restrict__ W1,   // [128,64] layer slice
    const float* __restrict__ b1,   // [64]
    int cur, int nxt)
{
    __shared__ float sW[128 * 64];  // rows 0..63 = top, 64..127 = bot
    __shared__ float sB1[64];

    int tid = threadIdx.x;
    for (int i = tid; i < 128 * 64 / 4; i += blockDim.x)
        ((float4*)sW)[i] = ((const float4*)W1)[i];
    if (tid < 64) sB1[tid] = b1[tid];

    int gt = blockIdx.x * blockDim.x + tid;
    int gs = gridDim.x * blockDim.x;

    // zero row sums
    for (int n = gt; n < NN; n += gs) d_row[n] = 0.0f;
    // accumulator init: next <- cur (so spmm result lands as e_new directly)
    for (int i = gt; i < NN * (DD / 4); i += gs) {
        ((float4*)d_e[0][nxt])[i] = ((const float4*)d_e[0][cur])[i];
        ((float4*)d_e[1][nxt])[i] = ((const float4*)d_e[1][cur])[i];
        ((float4*)d_e[2][nxt])[i] = ((const float4*)d_e[2][cur])[i];
    }
    __syncthreads();

    int warp   = gt >> 5;
    int lane   = tid & 31;
    int nwarps = gs >> 5;
    const float* e1c = d_e[1][cur];
    int j = lane * 2;

    for (int n = warp; n < NN; n += nwarps) {
        float a = e1c[n * 64 + lane];
        float b = e1c[n * 64 + 32 + lane];
        float2 p = make_float2(sB1[j], sB1[j + 1]);  // fold edge b1 into P
        float2 q = make_float2(0.0f, 0.0f);
#pragma unroll
        for (int k = 0; k < 64; k++) {
            float v = __shfl_sync(0xffffffffu, (k < 32) ? a : b, k & 31);
            float2 wt = *(const float2*)&sW[k * 64 + j];
            float2 wb = *(const float2*)&sW[4096 + k * 64 + j];
            p.x = fmaf(v, wt.x, p.x); p.y = fmaf(v, wt.y, p.y);
            q.x = fmaf(v, wb.x, q.x); q.y = fmaf(v, wb.y, q.y);
        }
        *(float2*)&d_P[n * 64 + j] = p;
        *(float2*)&d_Q[n * 64 + j] = q;
    }
}

// ---------------------------------------------------------------------------
// K_node_gate: gate = sigmoid(gumbel + relu(e2@W1+b1)@W2 + b2); gated = gate*e2
// ---------------------------------------------------------------------------
__global__ __launch_bounds__(256) void k_node_gate(
    const float* __restrict__ W1,   // [64,64]
    const float* __restrict__ b1,   // [64]
    const float* __restrict__ W2,   // [64,64]
    const float* __restrict__ b2,   // [64]
    const float* __restrict__ gum,  // [N,64] layer slice
    int cur)
{
    __shared__ float sW1[64 * 64];
    __shared__ float sW2[64 * 64];
    __shared__ float sB1[64], sB2[64];

    int tid = threadIdx.x;
    for (int i = tid; i < 64 * 64 / 4; i += blockDim.x) {
        ((float4*)sW1)[i] = ((const float4*)W1)[i];
        ((float4*)sW2)[i] = ((const float4*)W2)[i];
    }
    if (tid < 64) { sB1[tid] = b1[tid]; sB2[tid] = b2[tid]; }
    __syncthreads();

    int gt = blockIdx.x * blockDim.x + tid;
    int gs = gridDim.x * blockDim.x;
    int warp = gt >> 5, lane = tid & 31, nwarps = gs >> 5;
    const float* e2c = d_e[2][cur];
    int j = lane * 2;

    for (int n = warp; n < NN; n += nwarps) {
        float a = e2c[n * 64 + lane];
        float b = e2c[n * 64 + 32 + lane];
        float2 h = make_float2(sB1[j], sB1[j + 1]);
#pragma unroll
        for (int k = 0; k < 64; k++) {
            float v = __shfl_sync(0xffffffffu, (k < 32) ? a : b, k & 31);
            float2 w1 = *(const float2*)&sW1[k * 64 + j];
            h.x = fmaf(v, w1.x, h.x); h.y = fmaf(v, w1.y, h.y);
        }
        h.x = fmaxf(h.x, 0.0f); h.y = fmaxf(h.y, 0.0f);

        float2 lg = make_float2(sB2[j], sB2[j + 1]);
#pragma unroll
        for (int k = 0; k < 64; k++) {
            // h[k] lives at lane k>>1, component k&1
            float hv = __shfl_sync(0xffffffffu, (k & 1) ? h.y : h.x, k >> 1);
            float2 w2 = *(const float2*)&sW2[k * 64 + j];
            lg.x = fmaf(hv, w2.x, lg.x); lg.y = fmaf(hv, w2.y, lg.y);
        }
        float2 gmv = *(const float2*)&gum[n * 64 + j];
        float gx = sigmoidf(gmv.x + lg.x);
        float gy = sigmoidf(gmv.y + lg.y);
        float2 x2 = *(const float2*)&e2c[n * 64 + j];
        float2 outv = make_float2(gx * x2.x, gy * x2.y);
        *(float2*)&d_gated[n * 64 + j] = outv;
    }
}

// ---------------------------------------------------------------------------
// K_edge_w: per edge: w = sigmoid(gum + relu(P[h]+Q[t])·W2 + b2);
//           row[h] += w.   16 threads per edge.
// ---------------------------------------------------------------------------
__global__ __launch_bounds__(256) void k_edge_w(
    const int* __restrict__ h_idx, const int* __restrict__ t_idx,
    const float* __restrict__ W2,   // [64] layer slice
    const float* __restrict__ b2p,  // scalar at [0]
    const float* __restrict__ gum)  // [E] layer slice
{
    __shared__ float sW2[64];
    if (threadIdx.x < 64) sW2[threadIdx.x] = W2[threadIdx.x];
    __syncthreads();

    int e = blockIdx.x * 16 + (threadIdx.x >> 4);
    if (e >= EE) return;
    int sub = threadIdx.x & 15;
    int j = sub * 4;

    int h = h_idx[e], t = t_idx[e];
    float4 p = *(const float4*)&d_P[h * 64 + j];
    float4 q = *(const float4*)&d_Q[t * 64 + j];
    float hx = fmaxf(p.x + q.x, 0.0f);
    float hy = fmaxf(p.y + q.y, 0.0f);
    float hz = fmaxf(p.z + q.z, 0.0f);
    float hw = fmaxf(p.w + q.w, 0.0f);
    float dot = hx * sW2[j] + hy * sW2[j + 1] + hz * sW2[j + 2] + hw * sW2[j + 3];
#pragma unroll
    for (int off = 8; off >= 1; off >>= 1)
        dot += __shfl_xor_sync(0xffffffffu, dot, off);

    if (sub == 0) {
        float z = gum[e] + dot + __ldg(b2p);
        float w = sigmoidf(z);
        d_w[e] = w;
        atomicAdd(&d_row[h], w);
    }
}

// ---------------------------------------------------------------------------
// K_vals: vals1[e] = w[e] / row[h[e]]   (in place in d_w)
// ---------------------------------------------------------------------------
__global__ void k_vals(const int* __restrict__ h_idx) {
    int e = blockIdx.x * blockDim.x + threadIdx.x;
    if (e >= EE) return;
    int h = h_idx[e];
    d_w[e] = d_w[e] / d_row[h];
}

// ---------------------------------------------------------------------------
// K_spmm: fused 3-branch scatter.  16 threads/edge, float4 lanes.
//   next0[h] += G*e0[t];  next1[h] += vals1*e1[t];  next2[h] += G*gated[t]
// (next buffers pre-initialized to cur, so they become e_new.)
// ---------------------------------------------------------------------------
__global__ __launch_bounds__(256) void k_spmm(
    const int* __restrict__ h_idx, const int* __restrict__ t_idx,
    const float* __restrict__ G, int cur, int nxt)
{
    int e = blockIdx.x * 16 + (threadIdx.x >> 4);
    if (e >= EE) return;
    int sub = threadIdx.x & 15;
    int j = sub * 4;

    int h = h_idx[e], t = t_idx[e];
    float g = G[e];
    float v1 = d_w[e];

    float4 f0 = *(const float4*)&d_e[0][cur][t * 64 + j];
    red_add_v4(&d_e[0][nxt][h * 64 + j], g * f0.x, g * f0.y, g * f0.z, g * f0.w);

    float4 f1 = *(const float4*)&d_e[1][cur][t * 64 + j];
    red_add_v4(&d_e[1][nxt][h * 64 + j], v1 * f1.x, v1 * f1.y, v1 * f1.z, v1 * f1.w);

    float4 f2 = *(const float4*)&d_gated[t * 64 + j];
    red_add_v4(&d_e[2][nxt][h * 64 + j], g * f2.x, g * f2.y, g * f2.z, g * f2.w);
}

// ---------------------------------------------------------------------------
// K_sacc: s[b] += e_new[b]  (into d_out)
// ---------------------------------------------------------------------------
__global__ void k_sacc(float4* __restrict__ out, int nxt) {
    int i = blockIdx.x * blockDim.x + threadIdx.x;
    const int per = NN * (DD / 4);
    if (i >= 3 * per) return;
    int b = i / per;
    int r = i - b * per;
    float4 v = ((const float4*)d_e[b][nxt])[r];
    float4 o = out[i];
    o.x += v.x; o.y += v.y; o.z += v.z; o.w += v.w;
    out[i] = o;
}

// ---------------------------------------------------------------------------
// Host launcher (graph-capturable: launches only)
// ---------------------------------------------------------------------------
extern "C" void kernel_launch(void* const* d_in, const int* in_sizes, int n_in,
                              void* d_out, int out_size) {
    const float* emb0 = (const float*)d_in[0];
    const int*   hI   = (const int*)  d_in[1];
    const int*   tI   = (const int*)  d_in[2];
    const float* G    = (const float*)d_in[3];
    const float* egum = (const float*)d_in[4];   // [L,E]
    const float* ngum = (const float*)d_in[5];   // [L,N,D]
    const float* eW1  = (const float*)d_in[6];   // [L,128,64]
    const float* eb1  = (const float*)d_in[7];   // [L,64]
    const float* eW2  = (const float*)d_in[8];   // [L,64,1]
    const float* eb2  = (const float*)d_in[9];   // [L,1]
    const float* mW1  = (const float*)d_in[10];  // [L,64,64]
    const float* mb1  = (const float*)d_in[11];  // [L,64]
    const float* mW2  = (const float*)d_in[12];  // [L,64,64]
    const float* mb2  = (const float*)d_in[13];  // [L,64]
    float* out = (float*)d_out;

    k_init<<<(NN * DD / 4 + 255) / 256, 256>>>((const float4*)emb0, (float4*)out);

    for (int i = 0; i < LLAYERS; i++) {
        int cur = i & 1;
        int nxt = cur ^ 1;
        k_node_pq<<<1184, 256>>>(eW1 + i * 128 * 64, eb1 + i * 64, cur, nxt);
        k_node_gate<<<1184, 256>>>(mW1 + i * 64 * 64, mb1 + i * 64,
                                   mW2 + i * 64 * 64, mb2 + i * 64,
                                   ngum + (size_t)i * NN * 64, cur);
        k_edge_w<<<(EE + 15) / 16, 256>>>(hI, tI, eW2 + i * 64, eb2 + i,
                                          egum + (size_t)i * EE);
        k_vals<<<(EE + 255) / 256, 256>>>(hI);
        k_spmm<<<(EE + 15) / 16, 256>>>(hI, tI, G, cur, nxt);
        k_sacc<<<(3 * NN * DD / 4 + 255) / 256, 256>>>((float4*)out, nxt);
    }
}

// round 2
// speedup vs baseline: 1.2650x; 1.2650x over previous
#include <cuda_runtime.h>

#define NN 100000      // nodes
#define DD 64          // feature dim
#define EE 800000      // edges
#define LLAYERS 2

// ---------------------------------------------------------------------------
// Scratch (device globals; no allocation anywhere)
// ---------------------------------------------------------------------------
__device__ float d_eb[3][2][NN * DD];  // [branch][layer buffer][N*D]
__device__ float d_P[NN * DD];         // e1 @ W1_top + b1
__device__ float d_Q[NN * DD];         // e1 @ W1_bot
__device__ float d_gated[NN * DD];     // gate * e2
__device__ int   d_deg[NN];
__device__ int   d_rowptr[NN];
__device__ int   d_cursor[NN];
__device__ int   d_csr_t[EE];
__device__ float d_csr_g[EE];
__device__ int   d_csr_eid[EE];

__device__ __forceinline__ float sigmoidf(float x) {
    return 1.0f / (1.0f + expf(-x));
}

// ---------------------------------------------------------------------------
// CSR build
// ---------------------------------------------------------------------------
__global__ void k_zero_deg() {
    int n = blockIdx.x * blockDim.x + threadIdx.x;
    if (n < NN) d_deg[n] = 0;
}

__global__ void k_count(const int* __restrict__ h_idx) {
    int e = blockIdx.x * blockDim.x + threadIdx.x;
    if (e < EE) atomicAdd(&d_deg[h_idx[e]], 1);
}

__global__ void k_scan() {
    __shared__ int s[1024];
    int t = threadIdx.x;
    const int C = (NN + 1023) / 1024;
    int base = t * C;
    int sum = 0;
    for (int i = 0; i < C; i++) {
        int n = base + i;
        if (n < NN) sum += d_deg[n];
    }
    s[t] = sum;
    __syncthreads();
    for (int off = 1; off < 1024; off <<= 1) {
        int v = (t >= off) ? s[t - off] : 0;
        __syncthreads();
        s[t] += v;
        __syncthreads();
    }
    int run = s[t] - sum;  // exclusive prefix
    for (int i = 0; i < C; i++) {
        int n = base + i;
        if (n < NN) {
            d_rowptr[n] = run;
            d_cursor[n] = run;
            run += d_deg[n];
        }
    }
}

__global__ void k_fill(const int* __restrict__ h_idx, const int* __restrict__ t_idx,
                       const float* __restrict__ G) {
    int e = blockIdx.x * blockDim.x + threadIdx.x;
    if (e >= EE) return;
    int h = h_idx[e];
    int pos = atomicAdd(&d_cursor[h], 1);
    d_csr_t[pos] = t_idx[e];
    d_csr_g[pos] = G[e];
    d_csr_eid[pos] = e;
}

// ---------------------------------------------------------------------------
// K_node_pq: P = e1 @ W1_top + b1 ; Q = e1 @ W1_bot.  4 nodes / warp.
// Lane owns output cols (2*lane, 2*lane+1).
// ---------------------------------------------------------------------------
__global__ __launch_bounds__(256) void k_node_pq(
    const float* __restrict__ e1c,
    const float* __restrict__ W1,   // [128,64] layer slice (top rows 0..63, bot 64..127)
    const float* __restrict__ b1)   // [64]
{
    __shared__ float sW[128 * 64];
    __shared__ float sB1[64];

    int tid = threadIdx.x;
    for (int i = tid; i < 128 * 64 / 4; i += blockDim.x)
        ((float4*)sW)[i] = ((const float4*)W1)[i];
    if (tid < 64) sB1[tid] = b1[tid];
    __syncthreads();

    int gwarp = (blockIdx.x * blockDim.x + tid) >> 5;
    int lane = tid & 31;
    int j = lane * 2;
    int n0 = gwarp * 4;  // 3125 blocks * 8 warps * 4 = 100000 exactly

    float a[4], b[4];
    float2 p[4], q[4];
#pragma unroll
    for (int m = 0; m < 4; m++) {
        a[m] = e1c[(n0 + m) * 64 + lane];
        b[m] = e1c[(n0 + m) * 64 + 32 + lane];
        p[m] = make_float2(sB1[j], sB1[j + 1]);
        q[m] = make_float2(0.0f, 0.0f);
    }
#pragma unroll
    for (int k = 0; k < 64; k++) {
        float2 wt = *(const float2*)&sW[k * 64 + j];
        float2 wb = *(const float2*)&sW[4096 + k * 64 + j];
#pragma unroll
        for (int m = 0; m < 4; m++) {
            float v = __shfl_sync(0xffffffffu, (k < 32) ? a[m] : b[m], k & 31);
            p[m].x = fmaf(v, wt.x, p[m].x); p[m].y = fmaf(v, wt.y, p[m].y);
            q[m].x = fmaf(v, wb.x, q[m].x); q[m].y = fmaf(v, wb.y, q[m].y);
        }
    }
#pragma unroll
    for (int m = 0; m < 4; m++) {
        *(float2*)&d_P[(n0 + m) * 64 + j] = p[m];
        *(float2*)&d_Q[(n0 + m) * 64 + j] = q[m];
    }
}

// ---------------------------------------------------------------------------
// K_node_gate: gate = sigmoid(gumbel + relu(e2@W1+b1)@W2 + b2); gated = gate*e2
// 4 nodes / warp.
// ---------------------------------------------------------------------------
__global__ __launch_bounds__(256) void k_node_gate(
    const float* __restrict__ e2c,
    const float* __restrict__ W1,   // [64,64]
    const float* __restrict__ b1,   // [64]
    const float* __restrict__ W2,   // [64,64]
    const float* __restrict__ b2,   // [64]
    const float* __restrict__ gum)  // [N,64] layer slice
{
    __shared__ float sW1[64 * 64];
    __shared__ float sW2[64 * 64];
    __shared__ float sB1[64], sB2[64];

    int tid = threadIdx.x;
    for (int i = tid; i < 64 * 64 / 4; i += blockDim.x) {
        ((float4*)sW1)[i] = ((const float4*)W1)[i];
        ((float4*)sW2)[i] = ((const float4*)W2)[i];
    }
    if (tid < 64) { sB1[tid] = b1[tid]; sB2[tid] = b2[tid]; }
    __syncthreads();

    int gwarp = (blockIdx.x * blockDim.x + tid) >> 5;
    int lane = tid & 31;
    int j = lane * 2;
    int n0 = gwarp * 4;

    float a[4], b[4];
    float2 h[4];
#pragma unroll
    for (int m = 0; m < 4; m++) {
        a[m] = e2c[(n0 + m) * 64 + lane];
        b[m] = e2c[(n0 + m) * 64 + 32 + lane];
        h[m] = make_float2(sB1[j], sB1[j + 1]);
    }
#pragma unroll
    for (int k = 0; k < 64; k++) {
        float2 w1 = *(const float2*)&sW1[k * 64 + j];
#pragma unroll
        for (int m = 0; m < 4; m++) {
            float v = __shfl_sync(0xffffffffu, (k < 32) ? a[m] : b[m], k & 31);
            h[m].x = fmaf(v, w1.x, h[m].x); h[m].y = fmaf(v, w1.y, h[m].y);
        }
    }
    float2 lg[4];
#pragma unroll
    for (int m = 0; m < 4; m++) {
        h[m].x = fmaxf(h[m].x, 0.0f); h[m].y = fmaxf(h[m].y, 0.0f);
        lg[m] = make_float2(sB2[j], sB2[j + 1]);
    }
#pragma unroll
    for (int k = 0; k < 64; k++) {
        float2 w2 = *(const float2*)&sW2[k * 64 + j];
#pragma unroll
        for (int m = 0; m < 4; m++) {
            float hv = __shfl_sync(0xffffffffu, (k & 1) ? h[m].y : h[m].x, k >> 1);
            lg[m].x = fmaf(hv, w2.x, lg[m].x); lg[m].y = fmaf(hv, w2.y, lg[m].y);
        }
    }
#pragma unroll
    for (int m = 0; m < 4; m++) {
        int n = n0 + m;
        float2 gmv = *(const float2*)&gum[n * 64 + j];
        float2 x2 = *(const float2*)&e2c[n * 64 + j];
        float gx = sigmoidf(gmv.x + lg[m].x);
        float gy = sigmoidf(gmv.y + lg[m].y);
        *(float2*)&d_gated[n * 64 + j] = make_float2(gx * x2.x, gy * x2.y);
    }
}

// ---------------------------------------------------------------------------
// K_layer_edge: fused per-node edge weights + row norm + 3-branch SpMM + residual.
// 16 threads per node, lane owns float4 column chunk j = 4*sub.
//   w_e   = sigmoid(gum[e] + relu(P[h]+Q[t])·W2 + b2)
//   e0n[h] = e0c[h] + Σ g·e0c[t]
//   e1n[h] = e1c[h] + (Σ w·e1c[t]) / Σ w
//   e2n[h] = e2c[h] + Σ g·gated[t]
// ---------------------------------------------------------------------------
__global__ __launch_bounds__(256) void k_layer_edge(
    const float* __restrict__ e0c, const float* __restrict__ e1c,
    const float* __restrict__ e2c,
    float* __restrict__ e0n, float* __restrict__ e1n, float* __restrict__ e2n,
    const float* __restrict__ W2,   // [64] layer slice
    const float* __restrict__ b2p,  // scalar
    const float* __restrict__ gum)  // [E] layer slice
{
    __shared__ float sW2[64];
    if (threadIdx.x < 64) sW2[threadIdx.x] = W2[threadIdx.x];
    __syncthreads();

    int node = blockIdx.x * 16 + (threadIdx.x >> 4);  // 6250 blocks * 16 = 100000
    int sub = threadIdx.x & 15;
    int j = sub * 4;

    int start = d_rowptr[node];
    int deg = d_deg[node];
    float b2 = __ldg(b2p);

    float4 p = *(const float4*)&d_P[node * 64 + j];
    float4 wv = *(const float4*)&sW2[j];

    float rowsum = 0.0f;
    float4 a0 = make_float4(0.f, 0.f, 0.f, 0.f);
    float4 a1 = a0, a2 = a0;

    for (int it = 0; it < deg; it++) {
        int pos = start + it;
        int t = d_csr_t[pos];
        int eid = d_csr_eid[pos];
        float g = d_csr_g[pos];

        float4 q = *(const float4*)&d_Q[t * 64 + j];
        float rx = fmaxf(p.x + q.x, 0.0f);
        float ry = fmaxf(p.y + q.y, 0.0f);
        float rz = fmaxf(p.z + q.z, 0.0f);
        float rw = fmaxf(p.w + q.w, 0.0f);
        float dot = rx * wv.x + ry * wv.y + rz * wv.z + rw * wv.w;
#pragma unroll
        for (int off = 8; off >= 1; off >>= 1)
            dot += __shfl_xor_sync(0xffffffffu, dot, off, 16);

        float w = sigmoidf(gum[eid] + dot + b2);
        rowsum += w;

        float4 f0 = *(const float4*)&e0c[t * 64 + j];
        a0.x = fmaf(g, f0.x, a0.x); a0.y = fmaf(g, f0.y, a0.y);
        a0.z = fmaf(g, f0.z, a0.z); a0.w = fmaf(g, f0.w, a0.w);
        float4 f1 = *(const float4*)&e1c[t * 64 + j];
        a1.x = fmaf(w, f1.x, a1.x); a1.y = fmaf(w, f1.y, a1.y);
        a1.z = fmaf(w, f1.z, a1.z); a1.w = fmaf(w, f1.w, a1.w);
        float4 f2 = *(const float4*)&d_gated[t * 64 + j];
        a2.x = fmaf(g, f2.x, a2.x); a2.y = fmaf(g, f2.y, a2.y);
        a2.z = fmaf(g, f2.z, a2.z); a2.w = fmaf(g, f2.w, a2.w);
    }

    float dinv = (rowsum > 0.0f) ? (1.0f / rowsum) : 0.0f;

    float4 c0 = *(const float4*)&e0c[node * 64 + j];
    float4 c1 = *(const float4*)&e1c[node * 64 + j];
    float4 c2 = *(const float4*)&e2c[node * 64 + j];

    float4 o0 = make_float4(c0.x + a0.x, c0.y + a0.y, c0.z + a0.z, c0.w + a0.w);
    float4 o1 = make_float4(fmaf(dinv, a1.x, c1.x), fmaf(dinv, a1.y, c1.y),
                            fmaf(dinv, a1.z, c1.z), fmaf(dinv, a1.w, c1.w));
    float4 o2 = make_float4(c2.x + a2.x, c2.y + a2.y, c2.z + a2.z, c2.w + a2.w);

    *(float4*)&e0n[node * 64 + j] = o0;
    *(float4*)&e1n[node * 64 + j] = o1;
    *(float4*)&e2n[node * 64 + j] = o2;
}

// ---------------------------------------------------------------------------
// K_finish: out[b] = emb0 + e_layer1[b] + e_layer2[b]
// (layer1 result in d_eb[b][0], layer2 result in d_eb[b][1])
// ---------------------------------------------------------------------------
__global__ void k_finish(const float4* __restrict__ emb0, float4* __restrict__ out) {
    int i = blockIdx.x * blockDim.x + threadIdx.x;
    const int per = NN * (DD / 4);
    if (i >= per) return;
    float4 e = emb0[i];
#pragma unroll
    for (int b = 0; b < 3; b++) {
        float4 v1 = ((const float4*)d_eb[b][0])[i];
        float4 v2 = ((const float4*)d_eb[b][1])[i];
        out[b * per + i] = make_float4(e.x + v1.x + v2.x, e.y + v1.y + v2.y,
                                       e.z + v1.z + v2.z, e.w + v1.w + v2.w);
    }
}

// ---------------------------------------------------------------------------
// Host launcher (graph-capturable: launches only)
// ---------------------------------------------------------------------------
extern "C" void kernel_launch(void* const* d_in, const int* in_sizes, int n_in,
                              void* d_out, int out_size) {
    const float* emb0 = (const float*)d_in[0];
    const int*   hI   = (const int*)  d_in[1];
    const int*   tI   = (const int*)  d_in[2];
    const float* G    = (const float*)d_in[3];
    const float* egum = (const float*)d_in[4];   // [L,E]
    const float* ngum = (const float*)d_in[5];   // [L,N,D]
    const float* eW1  = (const float*)d_in[6];   // [L,128,64]
    const float* eb1  = (const float*)d_in[7];   // [L,64]
    const float* eW2  = (const float*)d_in[8];   // [L,64,1]
    const float* eb2  = (const float*)d_in[9];   // [L,1]
    const float* mW1  = (const float*)d_in[10];  // [L,64,64]
    const float* mb1  = (const float*)d_in[11];  // [L,64]
    const float* mW2  = (const float*)d_in[12];  // [L,64,64]
    const float* mb2  = (const float*)d_in[13];  // [L,64]
    float* out = (float*)d_out;

    // CSR build (once per launch; deterministic up to within-row order)
    k_zero_deg<<<(NN + 255) / 256, 256>>>();
    k_count<<<(EE + 255) / 256, 256>>>(hI);
    k_scan<<<1, 1024>>>();
    k_fill<<<(EE + 255) / 256, 256>>>(hI, tI, G);

    static float* ebuf[3][2];  // host-side pointer table (addresses fixed)
    float* base;
    cudaGetSymbolAddress((void**)&base, d_eb);
    for (int b = 0; b < 3; b++)
        for (int s = 0; s < 2; s++)
            ebuf[b][s] = base + ((size_t)b * 2 + s) * (size_t)NN * DD;

    for (int i = 0; i < LLAYERS; i++) {
        const float* c0 = (i == 0) ? emb0 : ebuf[0][(i - 1) & 1];
        const float* c1 = (i == 0) ? emb0 : ebuf[1][(i - 1) & 1];
        const float* c2 = (i == 0) ? emb0 : ebuf[2][(i - 1) & 1];
        float* n0 = ebuf[0][i & 1];
        float* n1 = ebuf[1][i & 1];
        float* n2 = ebuf[2][i & 1];

        k_node_pq<<<3125, 256>>>(c1, eW1 + i * 128 * 64, eb1 + i * 64);
        k_node_gate<<<3125, 256>>>(c2, mW1 + i * 64 * 64, mb1 + i * 64,
                                   mW2 + i * 64 * 64, mb2 + i * 64,
                                   ngum + (size_t)i * NN * 64);
        k_layer_edge<<<6250, 256>>>(c0, c1, c2, n0, n1, n2,
                                    eW2 + i * 64, eb2 + i,
                                    egum + (size_t)i * EE);
    }

    k_finish<<<(NN * DD / 4 + 255) / 256, 256>>>((const float4*)emb0, (float4*)out);
}